// round 4
// baseline (speedup 1.0000x reference)
#include <cuda_runtime.h>
#include <math.h>

// BATCH=128, SEQ_LEN=4096, HIDDEN=512, WINDOW=7 (W2=49), GRID=256
#define HIDDEN   512
#define WINDOW   7
#define W2       (WINDOW * WINDOW)
#define NTHREADS 512
#define NWARPS   (NTHREADS / 32)
#define MAXW     4            // ceil(49/16)

__global__ __launch_bounds__(NTHREADS, 1)
void hilbert_attn_kernel(const float* __restrict__ q,      // (B,1,H)
                         const float* __restrict__ k,      // (B,S,H)
                         const float* __restrict__ v,      // (B,S,H)
                         const int*   __restrict__ qpos,   // (B,)
                         const float* __restrict__ dscale, // ()
                         const float* __restrict__ lbias,  // (W2,)
                         const int*   __restrict__ hcoords,// (MAX_SEQ,2)
                         const int*   __restrict__ hinv,   // (GRID,GRID)
                         float*       __restrict__ out,    // (B,H)
                         int S, int grid_n)
{
    const int b    = blockIdx.x;
    const int tid  = threadIdx.x;
    const int wid  = tid >> 5;
    const int lane = tid & 31;

    __shared__ float4   s_part[NWARPS * HIDDEN / 4];   // 32 KB, 16B aligned
    __shared__ float    s_lbias[W2];
    __shared__ int      s_pos[W2];
    __shared__ unsigned s_mask[2];
    __shared__ int      s_q2d[2];
    __shared__ float    s_scale;
    __shared__ float    s_esum[NWARPS];

    // ---- q into registers: thread covers h = c*128 + lane*4 .. +3 ----
    float4 qv[4];
    {
        const float4* qg = reinterpret_cast<const float4*>(q + (size_t)b * HIDDEN);
        #pragma unroll
        for (int c = 0; c < 4; ++c) qv[c] = qg[c * 32 + lane];
    }

    if (tid == 0) {
        int p = qpos[b];
        s_q2d[0] = hcoords[2 * p];
        s_q2d[1] = hcoords[2 * p + 1];
        s_scale  = dscale[0];
    }
    if (tid < W2) s_lbias[tid] = lbias[tid];
    if (tid < 2)  s_mask[tid]  = 0u;
    __syncthreads();

    // ---- neighbor positions (parallel) + validity bitmask ----
    if (tid < W2) {
        int dx = tid / WINDOW - (WINDOW / 2);
        int dy = tid % WINDOW - (WINDOW / 2);
        int nx = s_q2d[0] + dx;
        int ny = s_q2d[1] + dy;
        bool ing = (nx >= 0) & (nx < grid_n) & (ny >= 0) & (ny < grid_n);
        int pos = ing ? hinv[nx * grid_n + ny] : -1;
        bool valid = ing && (pos >= 0) && (pos < S);
        s_pos[tid] = valid ? pos : -1;
        if (valid) atomicOr(&s_mask[tid >> 5], 1u << (tid & 31));
    }
    __syncthreads();   // the only barrier before the main phase

    // ---- per-warp window set: w = wid + 16*j, j = 0..3 ----
    const unsigned m0 = s_mask[0], m1 = s_mask[1];
    const float scale = s_scale;

    int   mypos[MAXW];
    float myval[MAXW];   // 1.0 valid, 0.0 invalid
    float mylw[MAXW];    // log weight (0 for invalid — kept finite)

    #pragma unroll
    for (int j = 0; j < MAXW; ++j) {
        int w = wid + 16 * j;
        int p = (w < W2) ? s_pos[w] : -1;
        bool valid = (p >= 0);
        mypos[j] = valid ? p : 0;
        myval[j] = valid ? 1.0f : 0.0f;
        float lw = 0.0f;
        if (valid) {
            int c;
            if (w < 32) {
                unsigned mm = (w == 31) ? 0xffffffffu : ((2u << w) - 1u);
                c = __popc(m0 & mm) - 1;
            } else {
                unsigned mm = (2u << (w - 32)) - 1u;
                c = __popc(m0) + __popc(m1 & mm) - 1;
            }
            int dx = w / WINDOW - (WINDOW / 2);
            int dy = w % WINDOW - (WINDOW / 2);
            float dist = (float)(abs(dx) + abs(dy));
            lw = logf(__expf(-dist * scale) + s_lbias[c] + 1e-8f);
        }
        mylw[j] = lw;
    }

    const float* kb = k + (size_t)b * S * HIDDEN;
    const float* vb = v + (size_t)b * S * HIDDEN;
    const float4* kr[MAXW];
    const float4* vr[MAXW];
    #pragma unroll
    for (int j = 0; j < MAXW; ++j) {
        kr[j] = reinterpret_cast<const float4*>(kb + (size_t)mypos[j] * HIDDEN);
        vr[j] = reinterpret_cast<const float4*>(vb + (size_t)mypos[j] * HIDDEN);
    }

    // ---- dots: chunk-major, unconditional loads, high MLP ----
    float d[MAXW] = {0.f, 0.f, 0.f, 0.f};
    #pragma unroll
    for (int c = 0; c < 4; ++c) {
        float4 kk[MAXW];
        #pragma unroll
        for (int j = 0; j < MAXW; ++j) kk[j] = kr[j][c * 32 + lane];
        #pragma unroll
        for (int j = 0; j < MAXW; ++j)
            d[j] += kk[j].x * qv[c].x + kk[j].y * qv[c].y
                  + kk[j].z * qv[c].z + kk[j].w * qv[c].w;
    }

    // ---- 4 interleaved warp reduces ----
    #pragma unroll
    for (int off = 16; off > 0; off >>= 1) {
        #pragma unroll
        for (int j = 0; j < MAXW; ++j)
            d[j] += __shfl_xor_sync(0xffffffffu, d[j], off);
    }

    // ---- unnormalized exp weights (0 for invalid windows) ----
    const float inv_sqrt_h = 0.04419417382415922f; // 1/sqrt(512)
    float e[MAXW];
    float esum = 0.0f;
    #pragma unroll
    for (int j = 0; j < MAXW; ++j) {
        e[j] = myval[j] * __expf(d[j] * inv_sqrt_h + mylw[j]);
        esum += e[j];
    }

    // ---- weighted V accumulation: chunk-major, unconditional loads ----
    float4 acc[4];
    #pragma unroll
    for (int c = 0; c < 4; ++c) acc[c] = make_float4(0.f, 0.f, 0.f, 0.f);
    #pragma unroll
    for (int c = 0; c < 4; ++c) {
        float4 vv[MAXW];
        #pragma unroll
        for (int j = 0; j < MAXW; ++j) vv[j] = vr[j][c * 32 + lane];
        #pragma unroll
        for (int j = 0; j < MAXW; ++j) {
            acc[c].x += e[j] * vv[j].x;
            acc[c].y += e[j] * vv[j].y;
            acc[c].z += e[j] * vv[j].z;
            acc[c].w += e[j] * vv[j].w;
        }
    }

    // ---- cross-warp reduction ----
    {
        float4* sp = &s_part[wid * (HIDDEN / 4)];
        #pragma unroll
        for (int c = 0; c < 4; ++c) sp[c * 32 + lane] = acc[c];
        if (lane == 0) s_esum[wid] = esum;
    }
    __syncthreads();

    const float* s_part_f = reinterpret_cast<const float*>(s_part);
    float num = 0.0f;
    #pragma unroll
    for (int ww = 0; ww < NWARPS; ++ww) num += s_part_f[ww * HIDDEN + tid];
    float den = 0.0f;
    #pragma unroll
    for (int ww = 0; ww < NWARPS; ++ww) den += s_esum[ww];

    out[(size_t)b * HIDDEN + tid] = num / den;
}

extern "C" void kernel_launch(void* const* d_in, const int* in_sizes, int n_in,
                              void* d_out, int out_size)
{
    const float* q       = (const float*)d_in[0];
    const float* k       = (const float*)d_in[1];
    const float* v       = (const float*)d_in[2];
    const int*   qpos    = (const int*)d_in[3];
    const float* dscale  = (const float*)d_in[4];
    const float* lbias   = (const float*)d_in[5];
    const int*   hcoords = (const int*)d_in[6];
    const int*   hinv    = (const int*)d_in[7];
    float*       out     = (float*)d_out;

    int B = in_sizes[3];                      // 128
    int H = in_sizes[0] / B;                  // 512
    int S = in_sizes[1] / (B * H);            // 4096
    int inv_elems = in_sizes[7];              // grid*grid
    int grid_n = 1;
    while (grid_n * grid_n < inv_elems) grid_n <<= 1;  // 256

    hilbert_attn_kernel<<<B, NTHREADS>>>(q, k, v, qpos, dscale, lbias,
                                         hcoords, hinv, out, S, grid_n);
}